// round 9
// baseline (speedup 1.0000x reference)
#include <cuda_runtime.h>
#include <cuda_fp16.h>
#include <cstdint>

// Problem constants
#define BB   8192
#define DIN  2048
#define HH   2048
#define K1   4096   // IN + H
#define K2   2048   // IN

// ---------------------------------------------------------------------------
// Scratch
// ---------------------------------------------------------------------------
__device__ __align__(128) __half g_concat_f16[(size_t)BB * K1];  // [B, IN+H]
__device__ __align__(128) __half g_gw_f16[(size_t)HH * K1];      // [H, IN+H]
__device__ __align__(128) __half g_wi_f16[(size_t)HH * K2];      // [H, IN]

// Output layout (floats): new_h | concat | pre_gate | gate | values | pre_h
#define OFF_NEWH    ((size_t)0)
#define OFF_CONCAT  ((size_t)BB * HH)
#define OFF_PREGATE (OFF_CONCAT + (size_t)BB * K1)
#define OFF_GATE    (OFF_PREGATE + (size_t)BB * HH)
#define OFF_VALUES  (OFF_GATE + (size_t)BB * HH)
#define OFF_PREH    (OFF_VALUES + (size_t)BB * HH)

// ---------------------------------------------------------------------------
// Helpers
// ---------------------------------------------------------------------------
__device__ __forceinline__ uint2 pack4_f16(float4 v) {
    __half2 lo = __floats2half2_rn(v.x, v.y);
    __half2 hi = __floats2half2_rn(v.z, v.w);
    uint2 u;
    u.x = *reinterpret_cast<unsigned*>(&lo);
    u.y = *reinterpret_cast<unsigned*>(&hi);
    return u;
}
__device__ __forceinline__ void cp_async16(uint32_t saddr, const void* gptr) {
    asm volatile("cp.async.cg.shared.global [%0], [%1], 16;" :: "r"(saddr), "l"(gptr));
}

// ---------------------------------------------------------------------------
// Kernel 1: convert inputs to fp16 + emit concat_input output region
// ---------------------------------------------------------------------------
#define N0 ((size_t)BB * DIN / 4)
#define N1 ((size_t)BB * HH  / 4)
#define N2 ((size_t)HH * K1  / 4)
#define N3 ((size_t)HH * K2  / 4)
#define NTOT (N0 + N1 + N2 + N3)

__global__ void __launch_bounds__(256) convert_kernel(
    const float4* __restrict__ inp,
    const float4* __restrict__ st,
    const float4* __restrict__ gw,
    const float4* __restrict__ wi,
    float4* __restrict__ out_concat)
{
    size_t idx = (size_t)blockIdx.x * blockDim.x + threadIdx.x;
    if (idx >= NTOT) return;

    uint2* cf  = reinterpret_cast<uint2*>(g_concat_f16);
    uint2* gwf = reinterpret_cast<uint2*>(g_gw_f16);
    uint2* wif = reinterpret_cast<uint2*>(g_wi_f16);

    if (idx < N0) {
        float4 v = inp[idx];
        size_t row = idx >> 9;
        size_t c   = idx & 511;
        out_concat[row * 1024 + c] = v;
        cf[row * 1024 + c] = pack4_f16(v);
    } else if (idx < N0 + N1) {
        size_t i = idx - N0;
        float4 v = st[i];
        size_t row = i >> 9;
        size_t c   = i & 511;
        out_concat[row * 1024 + 512 + c] = v;
        cf[row * 1024 + 512 + c] = pack4_f16(v);
    } else if (idx < N0 + N1 + N2) {
        size_t i = idx - N0 - N1;
        gwf[i] = pack4_f16(gw[i]);
    } else {
        size_t i = idx - N0 - N1 - N2;
        wif[i] = pack4_f16(wi[i]);
    }
}

// ---------------------------------------------------------------------------
// GEMM: C[B,H] = A_f16[B,K] @ W_f16[H,K]^T, fused epilogues.
// CTA tile 256x128x32, 256 threads, warp grid 4x2, warp tile 64x64.
// 4-stage cp.async pipeline, ONE __syncthreads per k-step.
//   EPI==1 : A = concat (lda=K1, K=K1), W = gw  -> pre_gate, gate
//   EPI==2 : A = concat cols[0,2048) (lda=K1, K=K2), W = wi -> values,pre_h,new_h
// ---------------------------------------------------------------------------
#define MTILE    256
#define NTILE    128
#define ROWPITCH 40                              // halves per smem row (80 B)
#define A_BYTES  (MTILE * ROWPITCH * 2)          // 20480 B per stage
#define B_BYTES  (NTILE * ROWPITCH * 2)          // 10240 B per stage
#define STAGES   4
#define SB_BASE  (STAGES * A_BYTES)              // 81920
#define SMEM_TOTAL (STAGES * (A_BYTES + B_BYTES))// 122880 B

template<int KDIM, int EPI>
__global__ void __launch_bounds__(256, 1) gemm_kernel(
    const float* __restrict__ bias,
    const float* __restrict__ state,
    const float* __restrict__ gate_in,
    float* __restrict__ out0,
    float* __restrict__ out1,
    float* __restrict__ out2)
{
    extern __shared__ __align__(16) __half sm[];
    const uint32_t sbase = (uint32_t)__cvta_generic_to_shared(sm);

    const __half* __restrict__ A  = g_concat_f16;                     // lda = K1
    const __half* __restrict__ Bw = (EPI == 1) ? g_gw_f16 : g_wi_f16; // ldb = KDIM

    const int tid  = threadIdx.x;
    const int bm   = blockIdx.y;
    const int bn   = blockIdx.x;
    const int warp = tid >> 5;
    const int lane = tid & 31;
    const int wm   = warp & 3;    // rows wm*64 (0..3)
    const int wn   = warp >> 2;   // cols wn*64 (0..1)

    const int KT = KDIM / 32;

    float acc[4][8][4];
    #pragma unroll
    for (int i = 0; i < 4; i++)
        #pragma unroll
        for (int j = 0; j < 8; j++)
            #pragma unroll
            for (int k = 0; k < 4; k++) acc[i][j][k] = 0.f;

    // loader: A = 1024 16B-chunks (4/thread), B = 512 (2/thread)
    const int lrow0 = tid >> 2;          // 0..63, + i*64
    const int lcol  = (tid & 3) * 8;
    const uint32_t smo = (uint32_t)(lrow0 * ROWPITCH + lcol) * 2;

    auto load_tile = [&](int s, int kt) {
        const int k0 = kt * 32;
        const uint32_t sa = sbase + (uint32_t)s * A_BYTES;
        const uint32_t sb = sbase + SB_BASE + (uint32_t)s * B_BYTES;
        #pragma unroll
        for (int i = 0; i < 4; i++) {
            const int row = lrow0 + i * 64;
            cp_async16(sa + smo + (uint32_t)(i * 64 * ROWPITCH) * 2,
                       A + (size_t)(bm * MTILE + row) * K1 + k0 + lcol);
        }
        #pragma unroll
        for (int i = 0; i < 2; i++) {
            const int row = lrow0 + i * 64;
            cp_async16(sb + smo + (uint32_t)(i * 64 * ROWPITCH) * 2,
                       Bw + (size_t)(bn * NTILE + row) * KDIM + k0 + lcol);
        }
        asm volatile("cp.async.commit_group;");
    };

    load_tile(0, 0);
    load_tile(1, 1);
    load_tile(2, 2);

    const int lr   = lane & 15;
    const int lchi = (lane >> 4) * 8;
    const uint32_t aoff = (uint32_t)((wm * 64 + lr) * ROWPITCH + lchi) * 2;
    const uint32_t boff = (uint32_t)((wn * 64 + lr) * ROWPITCH + lchi) * 2;

    #pragma unroll 1
    for (int kt = 0; kt < KT; kt++) {
        const int s = kt & (STAGES - 1);
        asm volatile("cp.async.wait_group 2;" ::: "memory");
        __syncthreads();
        if (kt + 3 < KT) load_tile((kt + 3) & (STAGES - 1), kt + 3);
        else             asm volatile("cp.async.commit_group;");   // keep count moving

        const uint32_t sa = sbase + (uint32_t)s * A_BYTES;
        const uint32_t sb = sbase + SB_BASE + (uint32_t)s * B_BYTES;

        #pragma unroll
        for (int kk = 0; kk < 2; kk++) {
            const uint32_t kb = (uint32_t)(kk * 16) * 2;
            uint32_t aa[4][4], bb[4][4];
            #pragma unroll
            for (int mt = 0; mt < 4; mt++) {
                uint32_t ad = sa + aoff + kb + (uint32_t)(mt * 16 * ROWPITCH) * 2;
                asm volatile("ldmatrix.sync.aligned.m8n8.x4.shared.b16 {%0,%1,%2,%3}, [%4];"
                             : "=r"(aa[mt][0]), "=r"(aa[mt][1]), "=r"(aa[mt][2]), "=r"(aa[mt][3])
                             : "r"(ad));
            }
            #pragma unroll
            for (int l = 0; l < 4; l++) {
                uint32_t ad = sb + boff + kb + (uint32_t)(l * 16 * ROWPITCH) * 2;
                asm volatile("ldmatrix.sync.aligned.m8n8.x4.shared.b16 {%0,%1,%2,%3}, [%4];"
                             : "=r"(bb[l][0]), "=r"(bb[l][1]), "=r"(bb[l][2]), "=r"(bb[l][3])
                             : "r"(ad));
            }
            #pragma unroll
            for (int mt = 0; mt < 4; mt++) {
                #pragma unroll
                for (int n = 0; n < 8; n++) {
                    uint32_t b0 = bb[n >> 1][n & 1];
                    uint32_t b1 = bb[n >> 1][(n & 1) + 2];
                    asm volatile(
                        "mma.sync.aligned.m16n8k16.row.col.f32.f16.f16.f32 "
                        "{%0,%1,%2,%3}, {%4,%5,%6,%7}, {%8,%9}, {%0,%1,%2,%3};"
                        : "+f"(acc[mt][n][0]), "+f"(acc[mt][n][1]),
                          "+f"(acc[mt][n][2]), "+f"(acc[mt][n][3])
                        : "r"(aa[mt][0]), "r"(aa[mt][1]), "r"(aa[mt][2]), "r"(aa[mt][3]),
                          "r"(b0), "r"(b1));
                }
            }
        }
    }

    // ---- epilogue ----
    const int rbase = bm * MTILE + wm * 64 + (lane >> 2);
    const int cbase = bn * NTILE + wn * 64 + (lane & 3) * 2;

    #pragma unroll
    for (int mt = 0; mt < 4; mt++) {
        #pragma unroll
        for (int n = 0; n < 8; n++) {
            const int col = cbase + n * 8;
            #pragma unroll
            for (int h = 0; h < 2; h++) {
                const int r = rbase + mt * 16 + h * 8;
                const size_t off = (size_t)r * HH + col;
                const float x0 = acc[mt][n][h * 2 + 0];
                const float x1 = acc[mt][n][h * 2 + 1];
                if (EPI == 1) {
                    const float2 b2 = *reinterpret_cast<const float2*>(bias + col);
                    float p0 = x0 + b2.x, p1 = x1 + b2.y;
                    *reinterpret_cast<float2*>(out0 + off) = make_float2(p0, p1);  // pre_gate
                    float2 gt = make_float2(fminf(fmaxf(p0, 0.f), 1.f),
                                            fminf(fmaxf(p1, 0.f), 1.f));
                    *reinterpret_cast<float2*>(out1 + off) = gt;                   // gate
                } else {
                    const float2 g = *reinterpret_cast<const float2*>(gate_in + off);
                    const float2 s = *reinterpret_cast<const float2*>(state + off);
                    const float v0 = tanhf(x0);
                    const float v1 = tanhf(x1);
                    const float ph0 = s.x * (1.f - g.x) + v0 * g.x;
                    const float ph1 = s.y * (1.f - g.y) + v1 * g.y;
                    *reinterpret_cast<float2*>(out0 + off) = make_float2(v0, v1);          // values
                    *reinterpret_cast<float2*>(out1 + off) = make_float2(ph0, ph1);        // pre_h
                    *reinterpret_cast<float2*>(out2 + off) = make_float2(fmaxf(ph0, 0.f),
                                                                         fmaxf(ph1, 0.f)); // new_h
                }
            }
        }
    }
}

// ---------------------------------------------------------------------------
// Launch
// ---------------------------------------------------------------------------
extern "C" void kernel_launch(void* const* d_in, const int* in_sizes, int n_in,
                              void* d_out, int out_size)
{
    const float* input = (const float*)d_in[0];   // [B, IN]
    const float* state = (const float*)d_in[1];   // [B, H]
    const float* gw    = (const float*)d_in[2];   // [H, IN+H]
    const float* bias  = (const float*)d_in[3];   // [H]
    const float* wi    = (const float*)d_in[4];   // [H, IN]
    float* out = (float*)d_out;

    // 1) convert + concat copy
    {
        const int threads = 256;
        const int blocks = (int)((NTOT + threads - 1) / threads);
        convert_kernel<<<blocks, threads>>>(
            (const float4*)input, (const float4*)state,
            (const float4*)gw, (const float4*)wi,
            (float4*)(out + OFF_CONCAT));
    }

    static bool attr_set = false;
    if (!attr_set) {
        cudaFuncSetAttribute(gemm_kernel<K1, 1>,
                             cudaFuncAttributeMaxDynamicSharedMemorySize, SMEM_TOTAL);
        cudaFuncSetAttribute(gemm_kernel<K2, 2>,
                             cudaFuncAttributeMaxDynamicSharedMemorySize, SMEM_TOTAL);
        attr_set = true;
    }

    // 2) GEMM1: pre_gate / gate  (K=4096)
    {
        dim3 grid(HH / NTILE, BB / MTILE);   // (16, 32)
        gemm_kernel<K1, 1><<<grid, 256, SMEM_TOTAL>>>(
            bias, nullptr, nullptr,
            out + OFF_PREGATE, out + OFF_GATE, nullptr);
    }

    // 3) GEMM2: values / pre_h / new_h  (K=2048)
    {
        dim3 grid(HH / NTILE, BB / MTILE);
        gemm_kernel<K2, 2><<<grid, 256, SMEM_TOTAL>>>(
            nullptr, state, out + OFF_GATE,
            out + OFF_VALUES, out + OFF_PREH, out + OFF_NEWH);
    }
}

// round 10
// speedup vs baseline: 1.2490x; 1.2490x over previous
#include <cuda_runtime.h>
#include <cuda_fp16.h>
#include <cstdint>

// Problem constants
#define BB   8192
#define DIN  2048
#define HH   2048
#define K1   4096   // IN + H
#define K2   2048   // IN

// ---------------------------------------------------------------------------
// Scratch
// ---------------------------------------------------------------------------
__device__ __align__(128) __half g_concat_f16[(size_t)BB * K1];  // [B, IN+H]
__device__ __align__(128) __half g_gw_f16[(size_t)HH * K1];      // [H, IN+H]
__device__ __align__(128) __half g_wi_f16[(size_t)HH * K2];      // [H, IN]

// Output layout (floats): new_h | concat | pre_gate | gate | values | pre_h
#define OFF_NEWH    ((size_t)0)
#define OFF_CONCAT  ((size_t)BB * HH)
#define OFF_PREGATE (OFF_CONCAT + (size_t)BB * K1)
#define OFF_GATE    (OFF_PREGATE + (size_t)BB * HH)
#define OFF_VALUES  (OFF_GATE + (size_t)BB * HH)
#define OFF_PREH    (OFF_VALUES + (size_t)BB * HH)

// ---------------------------------------------------------------------------
// Helpers
// ---------------------------------------------------------------------------
__device__ __forceinline__ uint2 pack4_f16(float4 v) {
    __half2 lo = __floats2half2_rn(v.x, v.y);
    __half2 hi = __floats2half2_rn(v.z, v.w);
    uint2 u;
    u.x = *reinterpret_cast<unsigned*>(&lo);
    u.y = *reinterpret_cast<unsigned*>(&hi);
    return u;
}
__device__ __forceinline__ void cp_async16(uint32_t saddr, const void* gptr) {
    asm volatile("cp.async.ca.shared.global [%0], [%1], 16;" :: "r"(saddr), "l"(gptr));
}

// ---------------------------------------------------------------------------
// Kernel 1: convert inputs to fp16 + emit concat_input output region
// ---------------------------------------------------------------------------
#define N0 ((size_t)BB * DIN / 4)
#define N1 ((size_t)BB * HH  / 4)
#define N2 ((size_t)HH * K1  / 4)
#define N3 ((size_t)HH * K2  / 4)
#define NTOT (N0 + N1 + N2 + N3)

__global__ void __launch_bounds__(256) convert_kernel(
    const float4* __restrict__ inp,
    const float4* __restrict__ st,
    const float4* __restrict__ gw,
    const float4* __restrict__ wi,
    float4* __restrict__ out_concat)
{
    size_t idx = (size_t)blockIdx.x * blockDim.x + threadIdx.x;
    if (idx >= NTOT) return;

    uint2* cf  = reinterpret_cast<uint2*>(g_concat_f16);
    uint2* gwf = reinterpret_cast<uint2*>(g_gw_f16);
    uint2* wif = reinterpret_cast<uint2*>(g_wi_f16);

    if (idx < N0) {
        float4 v = inp[idx];
        size_t row = idx >> 9;
        size_t c   = idx & 511;
        out_concat[row * 1024 + c] = v;
        cf[row * 1024 + c] = pack4_f16(v);
    } else if (idx < N0 + N1) {
        size_t i = idx - N0;
        float4 v = st[i];
        size_t row = i >> 9;
        size_t c   = i & 511;
        out_concat[row * 1024 + 512 + c] = v;
        cf[row * 1024 + 512 + c] = pack4_f16(v);
    } else if (idx < N0 + N1 + N2) {
        size_t i = idx - N0 - N1;
        gwf[i] = pack4_f16(gw[i]);
    } else {
        size_t i = idx - N0 - N1 - N2;
        wif[i] = pack4_f16(wi[i]);
    }
}

// ---------------------------------------------------------------------------
// GEMM1: pre_gate/gate. FP16 ACCUMULATORS (2x HMMA rate hypothesis).
// R6 geometry: tile 128x128x32, 256 threads, warp grid 4x2, warp tile 32x64,
// 2-stage cp.async, static smem.
// ---------------------------------------------------------------------------
__global__ void __launch_bounds__(256) gemm1_kernel(
    const float* __restrict__ bias,
    float* __restrict__ out_pregate,
    float* __restrict__ out_gate)
{
    __shared__ __align__(16) __half sA[2][128][40];
    __shared__ __align__(16) __half sB[2][128][40];

    const __half* __restrict__ A  = g_concat_f16;   // lda = K1
    const __half* __restrict__ Bw = g_gw_f16;       // ldb = K1

    const int tid  = threadIdx.x;
    const int bm   = blockIdx.y;
    const int bn   = blockIdx.x;
    const int warp = tid >> 5;
    const int lane = tid & 31;
    const int wm   = warp & 3;
    const int wn   = warp >> 2;

    const int KT = K1 / 32;

    // fp16 accumulators: 2 regs per m16n8 tile
    uint32_t acc[2][8][2];
    #pragma unroll
    for (int i = 0; i < 2; i++)
        #pragma unroll
        for (int j = 0; j < 8; j++) { acc[i][j][0] = 0u; acc[i][j][1] = 0u; }

    auto load_tile = [&](int buf, int kt) {
        const int k0 = kt * 32;
        #pragma unroll
        for (int i = 0; i < 2; i++) {
            int chunk = tid + i * 256;
            int row = chunk >> 2;
            int col = (chunk & 3) * 8;
            cp_async16((uint32_t)__cvta_generic_to_shared(&sA[buf][row][col]),
                       A + (size_t)(bm * 128 + row) * K1 + k0 + col);
            cp_async16((uint32_t)__cvta_generic_to_shared(&sB[buf][row][col]),
                       Bw + (size_t)(bn * 128 + row) * K1 + k0 + col);
        }
        asm volatile("cp.async.commit_group;");
    };

    load_tile(0, 0);

    #pragma unroll 1
    for (int kt = 0; kt < KT; kt++) {
        const int cur = kt & 1;
        if (kt + 1 < KT) {
            load_tile(cur ^ 1, kt + 1);
            asm volatile("cp.async.wait_group 1;");
        } else {
            asm volatile("cp.async.wait_group 0;");
        }
        __syncthreads();

        #pragma unroll
        for (int kk = 0; kk < 2; kk++) {
            uint32_t aa[2][4], bb[4][4];
            const int lr = lane & 15;
            const int lc = ((lane >> 4) * 8) + kk * 16;
            #pragma unroll
            for (int mt = 0; mt < 2; mt++) {
                uint32_t ad = (uint32_t)__cvta_generic_to_shared(&sA[cur][wm * 32 + mt * 16 + lr][lc]);
                asm volatile("ldmatrix.sync.aligned.m8n8.x4.shared.b16 {%0,%1,%2,%3}, [%4];"
                             : "=r"(aa[mt][0]), "=r"(aa[mt][1]), "=r"(aa[mt][2]), "=r"(aa[mt][3])
                             : "r"(ad));
            }
            #pragma unroll
            for (int l = 0; l < 4; l++) {
                uint32_t ad = (uint32_t)__cvta_generic_to_shared(&sB[cur][wn * 64 + l * 16 + lr][lc]);
                asm volatile("ldmatrix.sync.aligned.m8n8.x4.shared.b16 {%0,%1,%2,%3}, [%4];"
                             : "=r"(bb[l][0]), "=r"(bb[l][1]), "=r"(bb[l][2]), "=r"(bb[l][3])
                             : "r"(ad));
            }
            #pragma unroll
            for (int mt = 0; mt < 2; mt++) {
                #pragma unroll
                for (int n = 0; n < 8; n++) {
                    uint32_t b0 = bb[n >> 1][n & 1];
                    uint32_t b1 = bb[n >> 1][(n & 1) + 2];
                    asm volatile(
                        "mma.sync.aligned.m16n8k16.row.col.f16.f16.f16.f16 "
                        "{%0,%1}, {%2,%3,%4,%5}, {%6,%7}, {%0,%1};"
                        : "+r"(acc[mt][n][0]), "+r"(acc[mt][n][1])
                        : "r"(aa[mt][0]), "r"(aa[mt][1]), "r"(aa[mt][2]), "r"(aa[mt][3]),
                          "r"(b0), "r"(b1));
                }
            }
        }
        __syncthreads();
    }

    // ---- epilogue ----
    const int rbase = bm * 128 + wm * 32 + (lane >> 2);
    const int cbase = bn * 128 + wn * 64 + (lane & 3) * 2;

    #pragma unroll
    for (int mt = 0; mt < 2; mt++) {
        #pragma unroll
        for (int n = 0; n < 8; n++) {
            const int col = cbase + n * 8;
            const float2 b2 = *reinterpret_cast<const float2*>(bias + col);
            #pragma unroll
            for (int h = 0; h < 2; h++) {
                const int r = rbase + mt * 16 + h * 8;
                const size_t off = (size_t)r * HH + col;
                const __half2 hv = *reinterpret_cast<const __half2*>(&acc[mt][n][h]);
                const float2 x = __half22float2(hv);
                float p0 = x.x + b2.x, p1 = x.y + b2.y;
                *reinterpret_cast<float2*>(out_pregate + off) = make_float2(p0, p1);
                float2 gt = make_float2(fminf(fmaxf(p0, 0.f), 1.f),
                                        fminf(fmaxf(p1, 0.f), 1.f));
                *reinterpret_cast<float2*>(out_gate + off) = gt;
            }
        }
    }
}

// ---------------------------------------------------------------------------
// GEMM2: values/pre_h/new_h. FP32 accumulators (error-critical output).
// Same R6 geometry. A = concat cols [0,2048) (lda=K1, K=K2), W = wi.
// ---------------------------------------------------------------------------
__global__ void __launch_bounds__(256) gemm2_kernel(
    const float* __restrict__ state,
    const float* __restrict__ gate_in,
    float* __restrict__ out_values,
    float* __restrict__ out_preh,
    float* __restrict__ out_newh)
{
    __shared__ __align__(16) __half sA[2][128][40];
    __shared__ __align__(16) __half sB[2][128][40];

    const __half* __restrict__ A  = g_concat_f16;   // lda = K1
    const __half* __restrict__ Bw = g_wi_f16;       // ldb = K2

    const int tid  = threadIdx.x;
    const int bm   = blockIdx.y;
    const int bn   = blockIdx.x;
    const int warp = tid >> 5;
    const int lane = tid & 31;
    const int wm   = warp & 3;
    const int wn   = warp >> 2;

    const int KT = K2 / 32;

    float acc[2][8][4];
    #pragma unroll
    for (int i = 0; i < 2; i++)
        #pragma unroll
        for (int j = 0; j < 8; j++)
            #pragma unroll
            for (int k = 0; k < 4; k++) acc[i][j][k] = 0.f;

    auto load_tile = [&](int buf, int kt) {
        const int k0 = kt * 32;
        #pragma unroll
        for (int i = 0; i < 2; i++) {
            int chunk = tid + i * 256;
            int row = chunk >> 2;
            int col = (chunk & 3) * 8;
            cp_async16((uint32_t)__cvta_generic_to_shared(&sA[buf][row][col]),
                       A + (size_t)(bm * 128 + row) * K1 + k0 + col);
            cp_async16((uint32_t)__cvta_generic_to_shared(&sB[buf][row][col]),
                       Bw + (size_t)(bn * 128 + row) * K2 + k0 + col);
        }
        asm volatile("cp.async.commit_group;");
    };

    load_tile(0, 0);

    #pragma unroll 1
    for (int kt = 0; kt < KT; kt++) {
        const int cur = kt & 1;
        if (kt + 1 < KT) {
            load_tile(cur ^ 1, kt + 1);
            asm volatile("cp.async.wait_group 1;");
        } else {
            asm volatile("cp.async.wait_group 0;");
        }
        __syncthreads();

        #pragma unroll
        for (int kk = 0; kk < 2; kk++) {
            uint32_t aa[2][4], bb[4][4];
            const int lr = lane & 15;
            const int lc = ((lane >> 4) * 8) + kk * 16;
            #pragma unroll
            for (int mt = 0; mt < 2; mt++) {
                uint32_t ad = (uint32_t)__cvta_generic_to_shared(&sA[cur][wm * 32 + mt * 16 + lr][lc]);
                asm volatile("ldmatrix.sync.aligned.m8n8.x4.shared.b16 {%0,%1,%2,%3}, [%4];"
                             : "=r"(aa[mt][0]), "=r"(aa[mt][1]), "=r"(aa[mt][2]), "=r"(aa[mt][3])
                             : "r"(ad));
            }
            #pragma unroll
            for (int l = 0; l < 4; l++) {
                uint32_t ad = (uint32_t)__cvta_generic_to_shared(&sB[cur][wn * 64 + l * 16 + lr][lc]);
                asm volatile("ldmatrix.sync.aligned.m8n8.x4.shared.b16 {%0,%1,%2,%3}, [%4];"
                             : "=r"(bb[l][0]), "=r"(bb[l][1]), "=r"(bb[l][2]), "=r"(bb[l][3])
                             : "r"(ad));
            }
            #pragma unroll
            for (int mt = 0; mt < 2; mt++) {
                #pragma unroll
                for (int n = 0; n < 8; n++) {
                    uint32_t b0 = bb[n >> 1][n & 1];
                    uint32_t b1 = bb[n >> 1][(n & 1) + 2];
                    asm volatile(
                        "mma.sync.aligned.m16n8k16.row.col.f32.f16.f16.f32 "
                        "{%0,%1,%2,%3}, {%4,%5,%6,%7}, {%8,%9}, {%0,%1,%2,%3};"
                        : "+f"(acc[mt][n][0]), "+f"(acc[mt][n][1]),
                          "+f"(acc[mt][n][2]), "+f"(acc[mt][n][3])
                        : "r"(aa[mt][0]), "r"(aa[mt][1]), "r"(aa[mt][2]), "r"(aa[mt][3]),
                          "r"(b0), "r"(b1));
                }
            }
        }
        __syncthreads();
    }

    // ---- epilogue ----
    const int rbase = bm * 128 + wm * 32 + (lane >> 2);
    const int cbase = bn * 128 + wn * 64 + (lane & 3) * 2;

    #pragma unroll
    for (int mt = 0; mt < 2; mt++) {
        #pragma unroll
        for (int n = 0; n < 8; n++) {
            const int col = cbase + n * 8;
            #pragma unroll
            for (int h = 0; h < 2; h++) {
                const int r = rbase + mt * 16 + h * 8;
                const size_t off = (size_t)r * HH + col;
                const float x0 = acc[mt][n][h * 2 + 0];
                const float x1 = acc[mt][n][h * 2 + 1];
                const float2 g = *reinterpret_cast<const float2*>(gate_in + off);
                const float2 s = *reinterpret_cast<const float2*>(state + off);
                const float v0 = tanhf(x0);
                const float v1 = tanhf(x1);
                const float ph0 = s.x * (1.f - g.x) + v0 * g.x;
                const float ph1 = s.y * (1.f - g.y) + v1 * g.y;
                *reinterpret_cast<float2*>(out_values + off) = make_float2(v0, v1);
                *reinterpret_cast<float2*>(out_preh + off)   = make_float2(ph0, ph1);
                *reinterpret_cast<float2*>(out_newh + off)   = make_float2(fmaxf(ph0, 0.f),
                                                                           fmaxf(ph1, 0.f));
            }
        }
    }
}

// ---------------------------------------------------------------------------
// Launch
// ---------------------------------------------------------------------------
extern "C" void kernel_launch(void* const* d_in, const int* in_sizes, int n_in,
                              void* d_out, int out_size)
{
    const float* input = (const float*)d_in[0];   // [B, IN]
    const float* state = (const float*)d_in[1];   // [B, H]
    const float* gw    = (const float*)d_in[2];   // [H, IN+H]
    const float* bias  = (const float*)d_in[3];   // [H]
    const float* wi    = (const float*)d_in[4];   // [H, IN]
    float* out = (float*)d_out;

    // 1) convert + concat copy
    {
        const int threads = 256;
        const int blocks = (int)((NTOT + threads - 1) / threads);
        convert_kernel<<<blocks, threads>>>(
            (const float4*)input, (const float4*)state,
            (const float4*)gw, (const float4*)wi,
            (float4*)(out + OFF_CONCAT));
    }

    // 2) GEMM1 (fp16 acc): pre_gate / gate
    {
        dim3 grid(HH / 128, BB / 128);   // (16, 64)
        gemm1_kernel<<<grid, 256>>>(bias, out + OFF_PREGATE, out + OFF_GATE);
    }

    // 3) GEMM2 (fp32 acc): values / pre_h / new_h
    {
        dim3 grid(HH / 128, BB / 128);
        gemm2_kernel<<<grid, 256>>>(state, out + OFF_GATE,
                                    out + OFF_VALUES, out + OFF_PREH, out + OFF_NEWH);
    }
}